// round 10
// baseline (speedup 1.0000x reference)
#include <cuda_runtime.h>

typedef unsigned long long u64;

// ---------------------------------------------------------------------------
// Packed fp32x2 helpers (sm_100-family: 2x fp32 throughput packed pipe)
// ---------------------------------------------------------------------------
union F2 {
    u64    u;
    float2 f;
};

static __device__ __forceinline__ u64 pk2(float lo, float hi) {
    F2 r;
    r.f = make_float2(lo, hi);
    return r.u;
}
static __device__ __forceinline__ u64 ffma2(u64 a, u64 b, u64 c) {
    u64 d;
    asm("fma.rn.f32x2 %0, %1, %2, %3;" : "=l"(d) : "l"(a), "l"(b), "l"(c));
    return d;
}
static __device__ __forceinline__ float sigf(float z) {
    return __fdividef(1.0f, 1.0f + __expf(-z));
}

// ---------------------------------------------------------------------------
// Compile-time scalar constants
// ---------------------------------------------------------------------------
constexpr int NW4 = 738;   // packed float4 weight elements ({wj,wj,wj+1,wj+1})
constexpr int NB  = 109;   // packed {b,b} bias elements

constexpr int THREADS = 128;
constexpr int ROWS_PER_BLOCK = 4 * THREADS;   // 4 rows/thread (2 packed row-pairs)

struct Params {
    const float* W[10];
    const float* b[10];
};

// ---------------------------------------------------------------------------
// Partial layer: j2 range [J2B, J2B+J2N) of a layer with OUT outputs.
// Weight columns are DISJOINT across passes -> every weight still loaded
// exactly once (no extra L1 wavefronts). Splitting halves accumulator
// liveness, cutting peak registers so 3 CTAs/SM fit.
// ---------------------------------------------------------------------------
template <int IN, int OUT, int J2B, int J2N, bool RELU>
static __device__ __forceinline__ void layer_part(
    const ulonglong2* __restrict__ sw, const float2* __restrict__ sb,
    const F2* in0, const F2* in1, F2* out0, F2* out1)
{
    constexpr int H = OUT / 2;   // j2 stride in the weight array

    // Bias init for this half only
#pragma unroll
    for (int j2 = 0; j2 < J2N; ++j2) {
        const int j = 2 * (J2B + j2);
        const u64 b0 = *reinterpret_cast<const u64*>(sb + j);
        const u64 b1 = *reinterpret_cast<const u64*>(sb + j + 1);
        out0[j].u     = b0;  out1[j].u     = b0;
        out0[j + 1].u = b1;  out1[j + 1].u = b1;
    }

#pragma unroll
    for (int k = 0; k < IN; ++k) {
        const u64 x0 = in0[k].u;
        const u64 x1 = in1[k].u;
#pragma unroll
        for (int j2 = 0; j2 < J2N; ++j2) {
            const ulonglong2 w = sw[k * H + J2B + j2];   // one LDS.128
            const int j = 2 * (J2B + j2);
            out0[j].u     = ffma2(x0, w.x, out0[j].u);
            out1[j].u     = ffma2(x1, w.x, out1[j].u);
            out0[j + 1].u = ffma2(x0, w.y, out0[j + 1].u);
            out1[j + 1].u = ffma2(x1, w.y, out1[j + 1].u);
        }
    }

    if (RELU) {
#pragma unroll
        for (int j2 = 0; j2 < J2N; ++j2) {
            const int j = 2 * (J2B + j2);
#pragma unroll
            for (int d = 0; d < 2; ++d) {
                out0[j + d].f.x = fmaxf(out0[j + d].f.x, 0.0f);
                out0[j + d].f.y = fmaxf(out0[j + d].f.y, 0.0f);
                out1[j + d].f.x = fmaxf(out1[j + d].f.x, 0.0f);
                out1[j + d].f.y = fmaxf(out1[j + d].f.y, 0.0f);
            }
        }
    }
}

// Full layer: optionally j-blocked into two disjoint halves.
template <int IN, int OUT, bool RELU, bool SPLIT>
static __device__ __forceinline__ void layer(
    const ulonglong2* __restrict__ sw, const float2* __restrict__ sb,
    const F2* in0, const F2* in1, F2* out0, F2* out1)
{
    static_assert(OUT % 2 == 0, "even OUT only");
    constexpr int H  = OUT / 2;
    if constexpr (SPLIT) {
        constexpr int H0 = (H + 1) / 2;
        layer_part<IN, OUT, 0,  H0,     RELU>(sw, sb, in0, in1, out0, out1);
        layer_part<IN, OUT, H0, H - H0, RELU>(sw, sb, in0, in1, out0, out1);
    } else {
        layer_part<IN, OUT, 0, H, RELU>(sw, sb, in0, in1, out0, out1);
    }
}

__global__ void __launch_bounds__(THREADS, 3)
mlp_fused_kernel(const float* __restrict__ x, float* __restrict__ out,
                 Params p, int rows)
{
    // Function-local constexpr arrays (legal in device code, fully folded).
    constexpr int DIMS[11]  = {8, 20, 18, 16, 14, 12, 10, 8, 6, 4, 1};
    constexpr int WOFF4[10] = {0, 80, 260, 404, 516, 600, 660, 700, 724, 736};
    constexpr int BOFF[10]  = {0, 20, 38, 54, 68, 80, 90, 98, 104, 108};

    __shared__ ulonglong2 sW[NW4];   // {wj,wj,wj+1,wj+1} per element (16B aligned)
    __shared__ float2     sB[NB];    // {b,b}

    const int tid = threadIdx.x;

    // --- Stage packed weights + biases into shared memory -----------------
#pragma unroll
    for (int l = 0; l < 9; ++l) {
        const int OUT = DIMS[l + 1];
        const int n4  = DIMS[l] * OUT / 2;
        for (int i = tid; i < n4; i += THREADS) {
            const int k  = i / (OUT / 2);
            const int j2 = i % (OUT / 2);
            const float w0 = p.W[l][k * OUT + 2 * j2];
            const float w1 = p.W[l][k * OUT + 2 * j2 + 1];
            F2 a, b; a.f = make_float2(w0, w0); b.f = make_float2(w1, w1);
            sW[WOFF4[l] + i] = make_ulonglong2(a.u, b.u);
        }
        if (tid < OUT) {
            const float bb = p.b[l][tid];
            sB[BOFF[l] + tid] = make_float2(bb, bb);
        }
    }
    // Last layer (IN=4, OUT=1): pack pairs of k: {w_k,w_k,w_{k+1},w_{k+1}}
    if (tid < 2) {
        const float w0 = p.W[9][2 * tid];
        const float w1 = p.W[9][2 * tid + 1];
        F2 a, b; a.f = make_float2(w0, w0); b.f = make_float2(w1, w1);
        sW[WOFF4[9] + tid] = make_ulonglong2(a.u, b.u);
    }
    if (tid == 0) {
        const float bb = p.b[9][0];
        sB[BOFF[9]] = make_float2(bb, bb);
    }
    __syncthreads();

    // --- Row assignment: 4 rows per thread, coalesced ---------------------
    const long base = (long)blockIdx.x * ROWS_PER_BLOCK;
    const int r0 = (int)base + tid;
    const int r1 = r0 + THREADS;
    const int r2 = r0 + 2 * THREADS;
    const int r3 = r0 + 3 * THREADS;
    const bool g0 = r0 < rows, g1 = r1 < rows, g2 = r2 < rows, g3 = r3 < rows;

    const float4* __restrict__ X = (const float4*)x;
    const float4 z4 = make_float4(0.f, 0.f, 0.f, 0.f);
    float4 v0a = g0 ? X[2 * r0] : z4, v0b = g0 ? X[2 * r0 + 1] : z4;
    float4 v1a = g1 ? X[2 * r1] : z4, v1b = g1 ? X[2 * r1 + 1] : z4;
    float4 v2a = g2 ? X[2 * r2] : z4, v2b = g2 ? X[2 * r2 + 1] : z4;
    float4 v3a = g3 ? X[2 * r3] : z4, v3b = g3 ? X[2 * r3 + 1] : z4;

    // Two ping-pong register banks per row-pair (max layer width = 20)
    F2 A0[20], A1[20], B0[20], B1[20];

    // pair0 = rows (r0, r1); pair1 = rows (r2, r3)
    A0[0].u = pk2(v0a.x, v1a.x);  A1[0].u = pk2(v2a.x, v3a.x);
    A0[1].u = pk2(v0a.y, v1a.y);  A1[1].u = pk2(v2a.y, v3a.y);
    A0[2].u = pk2(v0a.z, v1a.z);  A1[2].u = pk2(v2a.z, v3a.z);
    A0[3].u = pk2(v0a.w, v1a.w);  A1[3].u = pk2(v2a.w, v3a.w);
    A0[4].u = pk2(v0b.x, v1b.x);  A1[4].u = pk2(v2b.x, v3b.x);
    A0[5].u = pk2(v0b.y, v1b.y);  A1[5].u = pk2(v2b.y, v3b.y);
    A0[6].u = pk2(v0b.z, v1b.z);  A1[6].u = pk2(v2b.z, v3b.z);
    A0[7].u = pk2(v0b.w, v1b.w);  A1[7].u = pk2(v2b.w, v3b.w);

    // --- 9 even-OUT fused layers (ping-pong A <-> B) ----------------------
    // Wide layers are j-blocked (SPLIT=true) to cap register liveness.
    layer< 8, 20, true, true >(sW + WOFF4[0], sB + BOFF[0], A0, A1, B0, B1);
    layer<20, 18, true, true >(sW + WOFF4[1], sB + BOFF[1], B0, B1, A0, A1);
    layer<18, 16, true, true >(sW + WOFF4[2], sB + BOFF[2], A0, A1, B0, B1);
    layer<16, 14, true, true >(sW + WOFF4[3], sB + BOFF[3], B0, B1, A0, A1);
    layer<14, 12, true, false>(sW + WOFF4[4], sB + BOFF[4], A0, A1, B0, B1);
    layer<12, 10, true, false>(sW + WOFF4[5], sB + BOFF[5], B0, B1, A0, A1);
    layer<10,  8, true, false>(sW + WOFF4[6], sB + BOFF[6], A0, A1, B0, B1);
    layer< 8,  6, true, false>(sW + WOFF4[7], sB + BOFF[7], B0, B1, A0, A1);
    layer< 6,  4, true, false>(sW + WOFF4[8], sB + BOFF[8], A0, A1, B0, B1);

    // --- Last layer: IN=4, OUT=1, k packed in pairs -----------------------
    u64 acc0, acc1;
    {
        const u64 bb = *reinterpret_cast<const u64*>(sB + BOFF[9]);
        acc0 = bb;  acc1 = bb;
        const ulonglong2 wA = (sW + WOFF4[9])[0];   // k=0,1
        const ulonglong2 wB = (sW + WOFF4[9])[1];   // k=2,3
        acc0 = ffma2(B0[0].u, wA.x, acc0);
        acc1 = ffma2(B1[0].u, wA.x, acc1);
        acc0 = ffma2(B0[1].u, wA.y, acc0);
        acc1 = ffma2(B1[1].u, wA.y, acc1);
        acc0 = ffma2(B0[2].u, wB.x, acc0);
        acc1 = ffma2(B1[2].u, wB.x, acc1);
        acc0 = ffma2(B0[3].u, wB.y, acc0);
        acc1 = ffma2(B1[3].u, wB.y, acc1);
    }

    // --- Sigmoid + store --------------------------------------------------
    F2 z0, z1;
    z0.u = acc0;  z1.u = acc1;
    if (g0) out[r0] = sigf(z0.f.x);
    if (g1) out[r1] = sigf(z0.f.y);
    if (g2) out[r2] = sigf(z1.f.x);
    if (g3) out[r3] = sigf(z1.f.y);
}

extern "C" void kernel_launch(void* const* d_in, const int* in_sizes, int n_in,
                              void* d_out, int out_size)
{
    const float* x = (const float*)d_in[0];
    Params p;
    for (int i = 0; i < 10; ++i) {
        p.W[i] = (const float*)d_in[1 + 2 * i];
        p.b[i] = (const float*)d_in[2 + 2 * i];
    }
    const int rows = in_sizes[0] / 8;   // x is [rows, 8] fp32
    const int grid = (rows + ROWS_PER_BLOCK - 1) / ROWS_PER_BLOCK;
    mlp_fused_kernel<<<grid, THREADS>>>(x, (float*)d_out, p, rows);
}

// round 11
// speedup vs baseline: 1.1650x; 1.1650x over previous
#include <cuda_runtime.h>

typedef unsigned long long u64;

// ---------------------------------------------------------------------------
// Packed fp32x2 helpers (sm_100-family: 2x fp32 throughput packed pipe)
// ---------------------------------------------------------------------------
union F2 {
    u64    u;
    float2 f;
};

static __device__ __forceinline__ u64 ffma2(u64 a, u64 b, u64 c) {
    u64 d;
    asm("fma.rn.f32x2 %0, %1, %2, %3;" : "=l"(d) : "l"(a), "l"(b), "l"(c));
    return d;
}
static __device__ __forceinline__ float sigf(float z) {
    return __fdividef(1.0f, 1.0f + __expf(-z));
}

// ---------------------------------------------------------------------------
// Compile-time scalar constants
// ---------------------------------------------------------------------------
constexpr int NW2 = 738;   // natural float2 weight pairs {W[k][2a], W[k][2a+1]}
constexpr int NB2 = 55;    // natural float2 bias pairs (+1 scalar slot)

constexpr int THREADS = 128;
constexpr int ROWS_PER_BLOCK = 4 * THREADS;   // 4 independent rows per thread

struct Params {
    const float* W[10];
    const float* b[10];
};

// ---------------------------------------------------------------------------
// Column-packed layer: accumulators hold OUTPUT pairs {z_2a, z_2a+1} per row.
// Weight operand = NATURAL float2 pair from smem (no duplication -> half the
// smem bytes of the row-packed scheme). Activation broadcast {x_k,x_k} is
// built in registers (cheap MOVs on the alu pipe, which has headroom).
// One LDS.64 feeds 4 FFMA2 (shared across the 4 rows).
// ---------------------------------------------------------------------------
template <int IN, int OUT, bool RELU>
static __device__ __forceinline__ void layer(
    const float2* __restrict__ sw, const float2* __restrict__ sb,
    F2 in[4][10], F2 out[4][10])
{
    static_assert(IN % 2 == 0 && OUT % 2 == 0, "even dims");
    constexpr int H = OUT / 2;

    // Bias init: one LDS.64 per output pair, replicated to 4 rows in regs
#pragma unroll
    for (int a = 0; a < H; ++a) {
        const u64 bb = *reinterpret_cast<const u64*>(sb + a);
#pragma unroll
        for (int r = 0; r < 4; ++r) out[r][a].u = bb;
    }

#pragma unroll
    for (int k = 0; k < IN; ++k) {
        // Broadcast x_k per row: {x,x} built in registers
        F2 xd[4];
#pragma unroll
        for (int r = 0; r < 4; ++r) {
            const float v = (k & 1) ? in[r][k >> 1].f.y : in[r][k >> 1].f.x;
            xd[r].f.x = v;
            xd[r].f.y = v;
        }
#pragma unroll
        for (int a = 0; a < H; ++a) {
            const u64 w = *reinterpret_cast<const u64*>(sw + k * H + a); // LDS.64, natural pair
#pragma unroll
            for (int r = 0; r < 4; ++r)
                out[r][a].u = ffma2(xd[r].u, w, out[r][a].u);
        }
    }

    if (RELU) {
#pragma unroll
        for (int a = 0; a < H; ++a)
#pragma unroll
            for (int r = 0; r < 4; ++r) {
                out[r][a].f.x = fmaxf(out[r][a].f.x, 0.0f);
                out[r][a].f.y = fmaxf(out[r][a].f.y, 0.0f);
            }
    }
}

__global__ void __launch_bounds__(THREADS, 2)
mlp_fused_kernel(const float* __restrict__ x, float* __restrict__ out,
                 Params p, int rows)
{
    // Function-local constexpr arrays (legal in device code, fully folded).
    constexpr int DIMS[11]  = {8, 20, 18, 16, 14, 12, 10, 8, 6, 4, 1};
    constexpr int WOFF2[10] = {0, 80, 260, 404, 516, 600, 660, 700, 724, 736};
    constexpr int BOFF2[9]  = {0, 10, 19, 27, 34, 40, 45, 49, 52};   // pairs; last-bias scalar at 54

    __shared__ float2 sW[NW2];   // natural {W[k][2a], W[k][2a+1]} pairs
    __shared__ float2 sB[NB2];   // natural {b_2a, b_2a+1} pairs; sB[54] = {b9, 0}

    const int tid = threadIdx.x;

    // --- Stage weights + biases (straight contiguous float2 copies) -------
#pragma unroll
    for (int l = 0; l < 9; ++l) {
        const int n2 = DIMS[l] * DIMS[l + 1] / 2;
        const float2* __restrict__ Wsrc = (const float2*)p.W[l];
        for (int i = tid; i < n2; i += THREADS)
            sW[WOFF2[l] + i] = Wsrc[i];
        if (tid < DIMS[l + 1] / 2)
            sB[BOFF2[l] + tid] = ((const float2*)p.b[l])[tid];
    }
    if (tid < 2)   // last layer W (4 floats = 2 natural pairs)
        sW[736 + tid] = ((const float2*)p.W[9])[tid];
    if (tid == 0)  // last layer bias as {b, 0}
        sB[54] = make_float2(p.b[9][0], 0.0f);
    __syncthreads();

    // --- Row assignment: 4 independent rows per thread, coalesced ---------
    const long base = (long)blockIdx.x * ROWS_PER_BLOCK;
    const int r0 = (int)base + tid;
    const int r1 = r0 + THREADS;
    const int r2 = r0 + 2 * THREADS;
    const int r3 = r0 + 3 * THREADS;
    const bool g0 = r0 < rows, g1 = r1 < rows, g2 = r2 < rows, g3 = r3 < rows;

    const float4* __restrict__ X = (const float4*)x;
    const float4 z4 = make_float4(0.f, 0.f, 0.f, 0.f);
    float4 va[4], vb[4];
    va[0] = g0 ? X[2 * r0] : z4;  vb[0] = g0 ? X[2 * r0 + 1] : z4;
    va[1] = g1 ? X[2 * r1] : z4;  vb[1] = g1 ? X[2 * r1 + 1] : z4;
    va[2] = g2 ? X[2 * r2] : z4;  vb[2] = g2 ? X[2 * r2 + 1] : z4;
    va[3] = g3 ? X[2 * r3] : z4;  vb[3] = g3 ? X[2 * r3 + 1] : z4;

    // Ping-pong banks: [row][pair], pair c = {z_2c, z_2c+1} (natural packing)
    F2 A[4][10], B[4][10];
#pragma unroll
    for (int r = 0; r < 4; ++r) {
        A[r][0].f = make_float2(va[r].x, va[r].y);
        A[r][1].f = make_float2(va[r].z, va[r].w);
        A[r][2].f = make_float2(vb[r].x, vb[r].y);
        A[r][3].f = make_float2(vb[r].z, vb[r].w);
    }

    // --- 9 even layers (ping-pong A <-> B) --------------------------------
    layer< 8, 20, true>(sW + WOFF2[0], sB + BOFF2[0], A, B);
    layer<20, 18, true>(sW + WOFF2[1], sB + BOFF2[1], B, A);
    layer<18, 16, true>(sW + WOFF2[2], sB + BOFF2[2], A, B);
    layer<16, 14, true>(sW + WOFF2[3], sB + BOFF2[3], B, A);
    layer<14, 12, true>(sW + WOFF2[4], sB + BOFF2[4], A, B);
    layer<12, 10, true>(sW + WOFF2[5], sB + BOFF2[5], B, A);
    layer<10,  8, true>(sW + WOFF2[6], sB + BOFF2[6], A, B);
    layer< 8,  6, true>(sW + WOFF2[7], sB + BOFF2[7], B, A);
    layer< 6,  4, true>(sW + WOFF2[8], sB + BOFF2[8], A, B);

    // --- Last layer (4 -> 1): natural pairs line up perfectly -------------
    // z = b + {x0,x1}.{W0,W1} + {x2,x3}.{W2,W3}  (packed mul, lane sum)
    const u64 w01 = *reinterpret_cast<const u64*>(sW + 736);
    const u64 w23 = *reinterpret_cast<const u64*>(sW + 737);
    const u64 bz  = *reinterpret_cast<const u64*>(sB + 54);   // {b, 0}
    float z[4];
#pragma unroll
    for (int r = 0; r < 4; ++r) {
        F2 t;
        t.u = ffma2(B[r][0].u, w01, bz);
        t.u = ffma2(B[r][1].u, w23, t.u);
        z[r] = t.f.x + t.f.y;
    }

    // --- Sigmoid + store --------------------------------------------------
    if (g0) out[r0] = sigf(z[0]);
    if (g1) out[r1] = sigf(z[1]);
    if (g2) out[r2] = sigf(z[2]);
    if (g3) out[r3] = sigf(z[3]);
}

extern "C" void kernel_launch(void* const* d_in, const int* in_sizes, int n_in,
                              void* d_out, int out_size)
{
    const float* x = (const float*)d_in[0];
    Params p;
    for (int i = 0; i < 10; ++i) {
        p.W[i] = (const float*)d_in[1 + 2 * i];
        p.b[i] = (const float*)d_in[2 + 2 * i];
    }
    const int rows = in_sizes[0] / 8;   // x is [rows, 8] fp32
    const int grid = (rows + ROWS_PER_BLOCK - 1) / ROWS_PER_BLOCK;
    mlp_fused_kernel<<<grid, THREADS>>>(x, (float*)d_out, p, rows);
}